// round 13
// baseline (speedup 1.0000x reference)
#include <cuda_runtime.h>

// 2-layer LSTM (H=51), B=512, T=512, scalar in, linear head, future=0.
// 128 persistent blocks, BB=4 rows, 672 threads (21 warps ~ 5/SMSP).
// 3-stage pipeline (R11 protocol): G1=Whh1+combine, G2=Wih2->zring, G3=Whh2+combine.
// Thread = 2 gates x 4 batches x k-half: w2[2][14] (56 regs), 28 broadcast LDS,
// xor-1 k-reduce + xor-2 gate exchange (R6 pattern), 1 cell update per thread.

#define H    51
#define HP   56
#define BHP  (4*HP)
#define TT   512
#define NTH  672
#define NBLK 128
#define NIT  513
#define ZS   816

#define BF1 1
#define BE1 2
#define BFZ 3
#define BEZ 4
#define BCNT 448

typedef unsigned long long ull;

__device__ __forceinline__ void bar_sync_n(int id) {
    asm volatile("bar.sync %0, %1;" :: "r"(id), "r"(BCNT) : "memory");
}
__device__ __forceinline__ void bar_arrive_n(int id) {
    asm volatile("bar.arrive %0, %1;" :: "r"(id), "r"(BCNT) : "memory");
}
__device__ __forceinline__ ull fma2(ull a, ull b, ull c) {
    ull d; asm("fma.rn.f32x2 %0, %1, %2, %3;" : "=l"(d) : "l"(a), "l"(b), "l"(c)); return d;
}
__device__ __forceinline__ ull pack2(float lo, float hi) {
    ull d; asm("mov.b64 %0, {%1, %2};" : "=l"(d) : "f"(lo), "f"(hi)); return d;
}
__device__ __forceinline__ float sum2(ull a) {
    float x, y; asm("mov.b64 {%0, %1}, %2;" : "=f"(x), "=f"(y) : "l"(a)); return x + y;
}
__device__ __forceinline__ float tanhap(float x) {
    float y; asm("tanh.approx.f32 %0, %1;" : "=f"(y) : "f"(x)); return y;
}
__device__ __forceinline__ float sigap(float x) {
    return fmaf(0.5f, tanhap(0.5f * x), 0.5f);
}

__global__ __launch_bounds__(NTH, 1)
void lstm2_kernel(const float* __restrict__ input,
                  const float* __restrict__ W_ih1,
                  const float* __restrict__ W_hh1,
                  const float* __restrict__ b_ih1,
                  const float* __restrict__ b_hh1,
                  const float* __restrict__ W_ih2,
                  const float* __restrict__ W_hh2,
                  const float* __restrict__ b_ih2,
                  const float* __restrict__ b_hh2,
                  const float* __restrict__ W_lin,
                  const float* __restrict__ b_lin,
                  float* __restrict__ out)
{
    __shared__ __align__(16) float hbuf[2*BHP + 8 + 2*BHP];
    __shared__ __align__(16) float zring[2*ZS];
    __shared__ float xall[4*TT];
    __shared__ float wlins[56];

    float* const h1b = hbuf;
    float* const h2b = hbuf + 2*BHP + 8;

    const int tid  = threadIdx.x;
    const int lane = tid & 31;
    const int wid  = tid >> 5;
    const int row0 = blockIdx.x * 4;

    const int grp  = (tid < 224) ? 0 : ((tid < 448) ? 1 : 2);
    const int l    = tid - grp*224;          // 0..223 within stage
    const bool act = (l < 204);
    const int unit = l >> 2;                 // 0..50
    const int gp   = (l >> 1) & 1;           // gate-pair: rows 2gp, 2gp+1
    const int ks   = l & 1;                  // k-half
    const bool isOut = (wid == 20) && (lane >= 16 && lane < 24);

    const unsigned pmask = 0x3u << (lane & 30);
    const unsigned qmask = 0xFu << (lane & 28);

    // ---- init smem ----
    for (int i = tid; i < 2*BHP + 8 + 2*BHP; i += NTH) hbuf[i] = 0.0f;
    for (int i = tid; i < 2*ZS; i += NTH) zring[i] = 0.0f;
    for (int i = tid; i < 4*TT; i += NTH) {
        const int b = i >> 9;
        const int t = i & (TT - 1);
        xall[i] = input[(row0 + b)*TT + t];
    }
    for (int i = tid; i < 56; i += NTH) wlins[i] = (i < H) ? W_lin[i] : 0.0f;

    // ---- weights -> registers: 2 gate rows x k-half as f32x2 ----
    ull w2[2][14];
    float bz[2] = {0.f, 0.f}, wx[2] = {0.f, 0.f};
    if (act) {
        const float* W = (grp == 0) ? W_hh1 : ((grp == 1) ? W_ih2 : W_hh2);
        #pragma unroll
        for (int e = 0; e < 2; ++e) {
            const int r = unit + 51*(2*gp + e);
            #pragma unroll
            for (int m = 0; m < 14; ++m) {
                const int k = ks*28 + 2*m;
                const float lo = (k   < H) ? W[r*H + k]     : 0.0f;
                const float hi = (k+1 < H) ? W[r*H + k + 1] : 0.0f;
                w2[e][m] = pack2(lo, hi);
            }
            if (grp == 0) { bz[e] = b_ih1[r] + b_hh1[r]; wx[e] = W_ih1[r]; }
            if (grp == 2) { bz[e] = b_ih2[r] + b_hh2[r]; }
        }
    }

    float blin = 0.0f; int ob = 0, half = 0;
    if (isOut) {
        const int o = lane - 16;
        ob = o >> 1; half = o & 1;
        blin = b_lin[0];
    }

    float cst = 0.f;
    __syncthreads();

    if (grp == 0) {
        // =============== G1: layer-1 recurrence ===============
        for (int t = 0; t < NIT; ++t) {
            const int sl = t & 1;
            bar_sync_n(sl ? (BE1 + 4) : BE1);
            if (act && t < TT) {
                const float* hp = h1b + (sl^1)*BHP + ks*28;   // h1(t-1)
                ull acc[2][4];
                #pragma unroll
                for (int e = 0; e < 2; ++e)
                    { acc[e][0]=0ull; acc[e][1]=0ull; acc[e][2]=0ull; acc[e][3]=0ull; }
                #pragma unroll
                for (int j = 0; j < 7; ++j) {
                    const ulonglong2 u0 = *reinterpret_cast<const ulonglong2*>(hp + 0*HP + 4*j);
                    const ulonglong2 u1 = *reinterpret_cast<const ulonglong2*>(hp + 1*HP + 4*j);
                    const ulonglong2 u2 = *reinterpret_cast<const ulonglong2*>(hp + 2*HP + 4*j);
                    const ulonglong2 u3 = *reinterpret_cast<const ulonglong2*>(hp + 3*HP + 4*j);
                    #pragma unroll
                    for (int e = 0; e < 2; ++e) {
                        acc[e][0] = fma2(w2[e][2*j],   u0.x, acc[e][0]);
                        acc[e][0] = fma2(w2[e][2*j+1], u0.y, acc[e][0]);
                        acc[e][1] = fma2(w2[e][2*j],   u1.x, acc[e][1]);
                        acc[e][1] = fma2(w2[e][2*j+1], u1.y, acc[e][1]);
                        acc[e][2] = fma2(w2[e][2*j],   u2.x, acc[e][2]);
                        acc[e][2] = fma2(w2[e][2*j+1], u2.y, acc[e][2]);
                        acc[e][3] = fma2(w2[e][2*j],   u3.x, acc[e][3]);
                        acc[e][3] = fma2(w2[e][2*j+1], u3.y, acc[e][3]);
                    }
                }
                // xor-1 k-reduce; keep batches {2ks, 2ks+1}
                float z[2][2];
                #pragma unroll
                for (int e = 0; e < 2; ++e)
                    #pragma unroll
                    for (int lb = 0; lb < 2; ++lb) {
                        const float mine  = sum2(ks ? acc[e][2+lb] : acc[e][lb]);
                        const float other = sum2(ks ? acc[e][lb]   : acc[e][2+lb]);
                        z[e][lb] = mine + __shfl_xor_sync(pmask, other, 1);
                    }
                // bias + x term per batch slot (before gate exchange)
                #pragma unroll
                for (int lb = 0; lb < 2; ++lb) {
                    const float xv = xall[(2*ks + lb)*TT + t];
                    #pragma unroll
                    for (int e = 0; e < 2; ++e)
                        z[e][lb] += fmaf(xv, wx[e], bz[e]);
                }
                // xor-2 gate exchange; final batch b = 2ks + gp
                const float r0 = __shfl_xor_sync(qmask, gp ? z[0][0] : z[0][1], 2);
                const float r1 = __shfl_xor_sync(qmask, gp ? z[1][0] : z[1][1], 2);
                const float m0 = gp ? z[0][1] : z[0][0];
                const float m1 = gp ? z[1][1] : z[1][0];
                const float zi = gp ? r0 : m0;
                const float zf = gp ? r1 : m1;
                const float zg = gp ? m0 : r0;
                const float zo = gp ? m1 : r1;
                const float ig = sigap(zi), fg = sigap(zf);
                const float gg = tanhap(zg), og = sigap(zo);
                cst = fmaf(fg, cst, ig*gg);
                h1b[sl*BHP + (2*ks + gp)*HP + unit] = og * tanhap(cst);
            }
            bar_arrive_n(sl ? (BF1 + 4) : BF1);
        }
    } else if (grp == 1) {
        // =============== G2: Wih2 * h1(t) -> z-ring ===============
        bar_arrive_n(BE1);
        bar_arrive_n(BE1 + 4);
        for (int t = 0; t < NIT; ++t) {
            const int sl = t & 1;
            bar_sync_n(sl ? (BF1 + 4) : BF1);
            bar_sync_n(sl ? (BEZ + 4) : BEZ);
            if (act && t < TT) {
                const float* hp = h1b + sl*BHP + ks*28;       // h1(t)
                ull acc[2][4];
                #pragma unroll
                for (int e = 0; e < 2; ++e)
                    { acc[e][0]=0ull; acc[e][1]=0ull; acc[e][2]=0ull; acc[e][3]=0ull; }
                #pragma unroll
                for (int j = 0; j < 7; ++j) {
                    const ulonglong2 u0 = *reinterpret_cast<const ulonglong2*>(hp + 0*HP + 4*j);
                    const ulonglong2 u1 = *reinterpret_cast<const ulonglong2*>(hp + 1*HP + 4*j);
                    const ulonglong2 u2 = *reinterpret_cast<const ulonglong2*>(hp + 2*HP + 4*j);
                    const ulonglong2 u3 = *reinterpret_cast<const ulonglong2*>(hp + 3*HP + 4*j);
                    #pragma unroll
                    for (int e = 0; e < 2; ++e) {
                        acc[e][0] = fma2(w2[e][2*j],   u0.x, acc[e][0]);
                        acc[e][0] = fma2(w2[e][2*j+1], u0.y, acc[e][0]);
                        acc[e][1] = fma2(w2[e][2*j],   u1.x, acc[e][1]);
                        acc[e][1] = fma2(w2[e][2*j+1], u1.y, acc[e][1]);
                        acc[e][2] = fma2(w2[e][2*j],   u2.x, acc[e][2]);
                        acc[e][2] = fma2(w2[e][2*j+1], u2.y, acc[e][2]);
                        acc[e][3] = fma2(w2[e][2*j],   u3.x, acc[e][3]);
                        acc[e][3] = fma2(w2[e][2*j+1], u3.y, acc[e][3]);
                    }
                }
                // xor-1 k-reduce; keep batches {2ks, 2ks+1}; store pre-exchange partials
                float4 zv;
                {
                    const float m00 = sum2(ks ? acc[0][2] : acc[0][0]);
                    const float o00 = sum2(ks ? acc[0][0] : acc[0][2]);
                    const float m01 = sum2(ks ? acc[0][3] : acc[0][1]);
                    const float o01 = sum2(ks ? acc[0][1] : acc[0][3]);
                    const float m10 = sum2(ks ? acc[1][2] : acc[1][0]);
                    const float o10 = sum2(ks ? acc[1][0] : acc[1][2]);
                    const float m11 = sum2(ks ? acc[1][3] : acc[1][1]);
                    const float o11 = sum2(ks ? acc[1][1] : acc[1][3]);
                    zv.x = m00 + __shfl_xor_sync(pmask, o00, 1);
                    zv.y = m01 + __shfl_xor_sync(pmask, o01, 1);
                    zv.z = m10 + __shfl_xor_sync(pmask, o10, 1);
                    zv.w = m11 + __shfl_xor_sync(pmask, o11, 1);
                }
                *reinterpret_cast<float4*>(zring + sl*ZS + 4*l) = zv;
            }
            bar_arrive_n(sl ? (BFZ + 4) : BFZ);
            bar_arrive_n(sl ? (BE1 + 4) : BE1);
        }
    } else {
        // =============== G3: Whh2 + combine; out-head ===============
        bar_arrive_n(BEZ);
        bar_arrive_n(BEZ + 4);
        for (int t = 0; t < NIT; ++t) {
            const int sl = t & 1;
            bar_sync_n(sl ? (BFZ + 4) : BFZ);
            if (act && t < TT) {
                const float* hp = h2b + (sl^1)*BHP + ks*28;   // h2(t-1)
                ull acc[2][4];
                #pragma unroll
                for (int e = 0; e < 2; ++e)
                    { acc[e][0]=0ull; acc[e][1]=0ull; acc[e][2]=0ull; acc[e][3]=0ull; }
                #pragma unroll
                for (int j = 0; j < 7; ++j) {
                    const ulonglong2 u0 = *reinterpret_cast<const ulonglong2*>(hp + 0*HP + 4*j);
                    const ulonglong2 u1 = *reinterpret_cast<const ulonglong2*>(hp + 1*HP + 4*j);
                    const ulonglong2 u2 = *reinterpret_cast<const ulonglong2*>(hp + 2*HP + 4*j);
                    const ulonglong2 u3 = *reinterpret_cast<const ulonglong2*>(hp + 3*HP + 4*j);
                    #pragma unroll
                    for (int e = 0; e < 2; ++e) {
                        acc[e][0] = fma2(w2[e][2*j],   u0.x, acc[e][0]);
                        acc[e][0] = fma2(w2[e][2*j+1], u0.y, acc[e][0]);
                        acc[e][1] = fma2(w2[e][2*j],   u1.x, acc[e][1]);
                        acc[e][1] = fma2(w2[e][2*j+1], u1.y, acc[e][1]);
                        acc[e][2] = fma2(w2[e][2*j],   u2.x, acc[e][2]);
                        acc[e][2] = fma2(w2[e][2*j+1], u2.y, acc[e][2]);
                        acc[e][3] = fma2(w2[e][2*j],   u3.x, acc[e][3]);
                        acc[e][3] = fma2(w2[e][2*j+1], u3.y, acc[e][3]);
                    }
                }
                float z[2][2];
                #pragma unroll
                for (int e = 0; e < 2; ++e)
                    #pragma unroll
                    for (int lb = 0; lb < 2; ++lb) {
                        const float mine  = sum2(ks ? acc[e][2+lb] : acc[e][lb]);
                        const float other = sum2(ks ? acc[e][lb]   : acc[e][2+lb]);
                        z[e][lb] = mine + __shfl_xor_sync(pmask, other, 1);
                    }
                // add Wih2 partials (identical lane mapping) + bias, pre-exchange
                const float4 zp = *reinterpret_cast<const float4*>(zring + sl*ZS + 4*l);
                z[0][0] += zp.x + bz[0];
                z[0][1] += zp.y + bz[0];
                z[1][0] += zp.z + bz[1];
                z[1][1] += zp.w + bz[1];
                // xor-2 gate exchange; final batch b = 2ks + gp
                const float r0 = __shfl_xor_sync(qmask, gp ? z[0][0] : z[0][1], 2);
                const float r1 = __shfl_xor_sync(qmask, gp ? z[1][0] : z[1][1], 2);
                const float m0 = gp ? z[0][1] : z[0][0];
                const float m1 = gp ? z[1][1] : z[1][0];
                const float zi = gp ? r0 : m0;
                const float zf = gp ? r1 : m1;
                const float zg = gp ? m0 : r0;
                const float zo = gp ? m1 : r1;
                const float ig = sigap(zi), fg = sigap(zf);
                const float gg = tanhap(zg), og = sigap(zo);
                cst = fmaf(fg, cst, ig*gg);
                h2b[sl*BHP + (2*ks + gp)*HP + unit] = og * tanhap(cst);
            }
            if (isOut && t >= 1) {
                const float* h2p = h2b + (sl^1)*BHP;          // h2(t-1)
                float v = 0.f;
                #pragma unroll
                for (int m = 0; m < 26; ++m)
                    v = fmaf(h2p[ob*HP + half*26 + m], wlins[half*26 + m], v);
                v += __shfl_xor_sync(pmask, v, 1);
                if (half == 0) out[(row0 + ob)*TT + (t - 1)] = v + blin;
            }
            bar_arrive_n(sl ? (BEZ + 4) : BEZ);
        }
    }
}

extern "C" void kernel_launch(void* const* d_in, const int* in_sizes, int n_in,
                              void* d_out, int out_size)
{
    const float* input = (const float*)d_in[0];
    const float* W_ih1 = (const float*)d_in[1];
    const float* W_hh1 = (const float*)d_in[2];
    const float* b_ih1 = (const float*)d_in[3];
    const float* b_hh1 = (const float*)d_in[4];
    const float* W_ih2 = (const float*)d_in[5];
    const float* W_hh2 = (const float*)d_in[6];
    const float* b_ih2 = (const float*)d_in[7];
    const float* b_hh2 = (const float*)d_in[8];
    const float* W_lin = (const float*)d_in[9];
    const float* b_lin = (const float*)d_in[10];
    float* out = (float*)d_out;

    lstm2_kernel<<<NBLK, NTH>>>(input, W_ih1, W_hh1, b_ih1, b_hh1,
                                W_ih2, W_hh2, b_ih2, b_hh2,
                                W_lin, b_lin, out);
}

// round 14
// speedup vs baseline: 1.1235x; 1.1235x over previous
#include <cuda_runtime.h>

// 2-layer LSTM (H=51), B=512, T=512, scalar in, linear head, future=0.
// 128 persistent blocks, BB=4 rows, 384 threads (12 warps = 3/SMSP).
// 3-stage pipeline, 1 warp/SMSP per stage:
//   G1 (w0-3):  Whh1*h1 + x*Wih1 + b1 -> combine -> h1(t)   [depth-4 h1 ring]
//   G2 (w4-7):  Wih2*h1(t) -> z-ring                        [depth-4 z ring]
//   G3 (w8-11): Whh2*h2(t-1) + z + b2 -> combine -> h2(t); out-head
// 16 named barriers: F1=0-3, E1=4-7, FZ=8-11, EZ=12-15 (count 256).
// Thread = 4 gates x 4 batches x k-half, weights in regs (f32x2), tanh.approx.

#define H    51
#define HP   56
#define BHP  (4*HP)
#define TT   512
#define NTH  384
#define NBLK 128
#define NIT  513
#define ZST  12                 // z floats per (unit,ks) row (16B aligned stride)
#define ZS   (102*ZST)          // 1224 floats per z slot

#define BF1 0
#define BE1 4
#define BFZ 8
#define BEZ 12
#define BCNT 256

typedef unsigned long long ull;

__device__ __forceinline__ void bar_sync_n(int id) {
    asm volatile("bar.sync %0, %1;" :: "r"(id), "r"(BCNT) : "memory");
}
__device__ __forceinline__ void bar_arrive_n(int id) {
    asm volatile("bar.arrive %0, %1;" :: "r"(id), "r"(BCNT) : "memory");
}
__device__ __forceinline__ ull fma2(ull a, ull b, ull c) {
    ull d; asm("fma.rn.f32x2 %0, %1, %2, %3;" : "=l"(d) : "l"(a), "l"(b), "l"(c)); return d;
}
__device__ __forceinline__ ull pack2(float lo, float hi) {
    ull d; asm("mov.b64 %0, {%1, %2};" : "=l"(d) : "f"(lo), "f"(hi)); return d;
}
__device__ __forceinline__ float sum2(ull a) {
    float x, y; asm("mov.b64 {%0, %1}, %2;" : "=f"(x), "=f"(y) : "l"(a)); return x + y;
}
__device__ __forceinline__ float tanhap(float x) {
    float y; asm("tanh.approx.f32 %0, %1;" : "=f"(y) : "f"(x)); return y;
}
__device__ __forceinline__ float sigap(float x) {
    return fmaf(0.5f, tanhap(0.5f * x), 0.5f);
}

__global__ __launch_bounds__(NTH, 1)
void lstm2_kernel(const float* __restrict__ input,
                  const float* __restrict__ W_ih1,
                  const float* __restrict__ W_hh1,
                  const float* __restrict__ b_ih1,
                  const float* __restrict__ b_hh1,
                  const float* __restrict__ W_ih2,
                  const float* __restrict__ W_hh2,
                  const float* __restrict__ b_ih2,
                  const float* __restrict__ b_hh2,
                  const float* __restrict__ W_lin,
                  const float* __restrict__ b_lin,
                  float* __restrict__ out)
{
    // h1: 4 slots of BHP; pad 8; h2: 2 slots of BHP
    __shared__ __align__(16) float hbuf[4*BHP + 8 + 2*BHP];
    __shared__ __align__(16) float zring[4*ZS];
    __shared__ float xall[4*TT];

    float* const h1b = hbuf;
    float* const h2b = hbuf + 4*BHP + 8;

    const int tid  = threadIdx.x;
    const int lane = tid & 31;
    const int wid  = tid >> 5;
    const int grp  = wid >> 2;      // 0=G1, 1=G2, 2=G3
    const int s    = wid & 3;       // SMSP
    const int row0 = blockIdx.x * 4;

    const unsigned pmask = 0x3u << (lane & 30);

    for (int i = tid; i < 4*BHP + 8 + 2*BHP; i += NTH) hbuf[i] = 0.0f;
    for (int i = tid; i < 4*ZS; i += NTH) zring[i] = 0.0f;
    for (int i = tid; i < 4*TT; i += NTH) {
        const int b = i >> 9;
        const int t = i & (TT - 1);
        xall[i] = input[(row0 + b)*TT + t];
    }

    const int ubase = 13 * s;
    const int NU    = (s < 3) ? 13 : 12;
    const bool act  = (lane < 2 * NU);
    const int unit  = ubase + (lane >> 1);
    const int ks    = lane & 1;
    const bool isOut = (grp == 2) && (s == 3) && (lane >= 24);

    ull w2[4][14];
    float bz[4] = {0,0,0,0}, wx[4] = {0,0,0,0};
    if (act) {
        const float* W = (grp == 0) ? W_hh1 : ((grp == 1) ? W_ih2 : W_hh2);
        #pragma unroll
        for (int g = 0; g < 4; ++g) {
            const int r = unit + 51*g;
            #pragma unroll
            for (int m = 0; m < 14; ++m) {
                const int k = ks*28 + 2*m;
                const float lo = (k   < H) ? W[r*H + k]     : 0.0f;
                const float hi = (k+1 < H) ? W[r*H + k + 1] : 0.0f;
                w2[g][m] = pack2(lo, hi);
            }
            if (grp == 0) { bz[g] = b_ih1[r] + b_hh1[r]; wx[g] = W_ih1[r]; }
            if (grp == 2) { bz[g] = b_ih2[r] + b_hh2[r]; }
        }
    }

    float wo[26]; float blin = 0.0f; int ob = 0, half = 0;
    if (isOut) {
        const int o = lane - 24;
        ob = o >> 1; half = o & 1;
        #pragma unroll
        for (int m = 0; m < 26; ++m) {
            const int j = half*26 + m;
            wo[m] = (j < H) ? W_lin[j] : 0.0f;
        }
        blin = b_lin[0];
    }

    float c1[2] = {0.f, 0.f};
    float c2[2] = {0.f, 0.f};
    const int zb = 2*unit + ks;     // z row 0..101

    __syncthreads();

    if (grp == 0) {
        // ================= G1 =================
        for (int t = 0; t < NIT; ++t) {
            const int sl = t & 3;
            bar_sync_n(BE1 + sl);                  // G2 consumed h1(t-4); G1 rendezvous
            if (act && t < TT) {
                const float* h1r = h1b + ((t + 3) & 3)*BHP;   // h1(t-1)
                float*       h1w = h1b + sl*BHP;              // h1(t)
                ull acc[4][4];
                #pragma unroll
                for (int g = 0; g < 4; ++g)
                    { acc[g][0]=0ull; acc[g][1]=0ull; acc[g][2]=0ull; acc[g][3]=0ull; }
                const float* hp = h1r + ks*28;
                #pragma unroll
                for (int j = 0; j < 7; ++j) {
                    const ulonglong2 u0 = *reinterpret_cast<const ulonglong2*>(hp + 0*HP + 4*j);
                    const ulonglong2 u1 = *reinterpret_cast<const ulonglong2*>(hp + 1*HP + 4*j);
                    const ulonglong2 u2 = *reinterpret_cast<const ulonglong2*>(hp + 2*HP + 4*j);
                    const ulonglong2 u3 = *reinterpret_cast<const ulonglong2*>(hp + 3*HP + 4*j);
                    #pragma unroll
                    for (int g = 0; g < 4; ++g) {
                        acc[g][0] = fma2(w2[g][2*j],   u0.x, acc[g][0]);
                        acc[g][0] = fma2(w2[g][2*j+1], u0.y, acc[g][0]);
                        acc[g][1] = fma2(w2[g][2*j],   u1.x, acc[g][1]);
                        acc[g][1] = fma2(w2[g][2*j+1], u1.y, acc[g][1]);
                        acc[g][2] = fma2(w2[g][2*j],   u2.x, acc[g][2]);
                        acc[g][2] = fma2(w2[g][2*j+1], u2.y, acc[g][2]);
                        acc[g][3] = fma2(w2[g][2*j],   u3.x, acc[g][3]);
                        acc[g][3] = fma2(w2[g][2*j+1], u3.y, acc[g][3]);
                    }
                }
                float fin[4][2];
                #pragma unroll
                for (int g = 0; g < 4; ++g)
                    #pragma unroll
                    for (int lb = 0; lb < 2; ++lb) {
                        const float mine  = sum2(ks ? acc[g][2+lb] : acc[g][lb]);
                        const float other = sum2(ks ? acc[g][lb]   : acc[g][2+lb]);
                        fin[g][lb] = mine + __shfl_xor_sync(pmask, other, 1);
                    }
                #pragma unroll
                for (int lb = 0; lb < 2; ++lb) {
                    const int b = 2*ks + lb;
                    const float xv = xall[b*TT + t];
                    const float zi = fmaf(xv, wx[0], fin[0][lb] + bz[0]);
                    const float zf = fmaf(xv, wx[1], fin[1][lb] + bz[1]);
                    const float zg = fmaf(xv, wx[2], fin[2][lb] + bz[2]);
                    const float zo = fmaf(xv, wx[3], fin[3][lb] + bz[3]);
                    const float ig = sigap(zi), fg = sigap(zf);
                    const float gg = tanhap(zg), og = sigap(zo);
                    c1[lb] = fmaf(fg, c1[lb], ig*gg);
                    h1w[b*HP + unit] = og * tanhap(c1[lb]);
                }
            }
            bar_arrive_n(BF1 + sl);                // h1(t) published
        }
    } else if (grp == 1) {
        // ================= G2 =================
        bar_arrive_n(BE1 + 0);
        bar_arrive_n(BE1 + 1);
        bar_arrive_n(BE1 + 2);
        bar_arrive_n(BE1 + 3);
        for (int t = 0; t < NIT; ++t) {
            const int sl = t & 3;
            bar_sync_n(BEZ + sl);                  // z slot free (stale; rarely waits)
            bar_sync_n(BF1 + sl);                  // h1(t) ready
            if (act && t < TT) {
                const float* h1r = h1b + sl*BHP;   // h1(t)
                ull acc[4][4];
                #pragma unroll
                for (int g = 0; g < 4; ++g)
                    { acc[g][0]=0ull; acc[g][1]=0ull; acc[g][2]=0ull; acc[g][3]=0ull; }
                const float* hp = h1r + ks*28;
                #pragma unroll
                for (int j = 0; j < 7; ++j) {
                    const ulonglong2 u0 = *reinterpret_cast<const ulonglong2*>(hp + 0*HP + 4*j);
                    const ulonglong2 u1 = *reinterpret_cast<const ulonglong2*>(hp + 1*HP + 4*j);
                    const ulonglong2 u2 = *reinterpret_cast<const ulonglong2*>(hp + 2*HP + 4*j);
                    const ulonglong2 u3 = *reinterpret_cast<const ulonglong2*>(hp + 3*HP + 4*j);
                    #pragma unroll
                    for (int g = 0; g < 4; ++g) {
                        acc[g][0] = fma2(w2[g][2*j],   u0.x, acc[g][0]);
                        acc[g][0] = fma2(w2[g][2*j+1], u0.y, acc[g][0]);
                        acc[g][1] = fma2(w2[g][2*j],   u1.x, acc[g][1]);
                        acc[g][1] = fma2(w2[g][2*j+1], u1.y, acc[g][1]);
                        acc[g][2] = fma2(w2[g][2*j],   u2.x, acc[g][2]);
                        acc[g][2] = fma2(w2[g][2*j+1], u2.y, acc[g][2]);
                        acc[g][3] = fma2(w2[g][2*j],   u3.x, acc[g][3]);
                        acc[g][3] = fma2(w2[g][2*j+1], u3.y, acc[g][3]);
                    }
                }
                // xor-1 k-reduce; pack 8 partials -> 2x STS.128
                float4 zlo, zhi;
                {
                    float zt[4][2];
                    #pragma unroll
                    for (int g = 0; g < 4; ++g)
                        #pragma unroll
                        for (int lb = 0; lb < 2; ++lb) {
                            const float mine  = sum2(ks ? acc[g][2+lb] : acc[g][lb]);
                            const float other = sum2(ks ? acc[g][lb]   : acc[g][2+lb]);
                            zt[g][lb] = mine + __shfl_xor_sync(pmask, other, 1);
                        }
                    zlo = make_float4(zt[0][0], zt[0][1], zt[1][0], zt[1][1]);
                    zhi = make_float4(zt[2][0], zt[2][1], zt[3][0], zt[3][1]);
                }
                float* zw = zring + sl*ZS + zb*ZST;
                reinterpret_cast<float4*>(zw)[0] = zlo;
                reinterpret_cast<float4*>(zw)[1] = zhi;
            }
            bar_arrive_n(BFZ + sl);                // z(t) published
            bar_arrive_n(BE1 + sl);                // h1(t) consumed
        }
    } else {
        // ================= G3 =================
        bar_arrive_n(BEZ + 0);
        bar_arrive_n(BEZ + 1);
        bar_arrive_n(BEZ + 2);
        bar_arrive_n(BEZ + 3);
        for (int t = 0; t < NIT; ++t) {
            const int sl = t & 3;
            bar_sync_n(BFZ + sl);                  // z(t) ready; G3 rendezvous
            if (act && t < TT) {
                const float* h2r = h2b + ((t + 1) & 1)*BHP;   // h2(t-1)
                float*       h2w = h2b + (t & 1)*BHP;         // h2(t)
                ull acc[4][4];
                #pragma unroll
                for (int g = 0; g < 4; ++g)
                    { acc[g][0]=0ull; acc[g][1]=0ull; acc[g][2]=0ull; acc[g][3]=0ull; }
                const float* hp = h2r + ks*28;
                #pragma unroll
                for (int j = 0; j < 7; ++j) {
                    const ulonglong2 u0 = *reinterpret_cast<const ulonglong2*>(hp + 0*HP + 4*j);
                    const ulonglong2 u1 = *reinterpret_cast<const ulonglong2*>(hp + 1*HP + 4*j);
                    const ulonglong2 u2 = *reinterpret_cast<const ulonglong2*>(hp + 2*HP + 4*j);
                    const ulonglong2 u3 = *reinterpret_cast<const ulonglong2*>(hp + 3*HP + 4*j);
                    #pragma unroll
                    for (int g = 0; g < 4; ++g) {
                        acc[g][0] = fma2(w2[g][2*j],   u0.x, acc[g][0]);
                        acc[g][0] = fma2(w2[g][2*j+1], u0.y, acc[g][0]);
                        acc[g][1] = fma2(w2[g][2*j],   u1.x, acc[g][1]);
                        acc[g][1] = fma2(w2[g][2*j+1], u1.y, acc[g][1]);
                        acc[g][2] = fma2(w2[g][2*j],   u2.x, acc[g][2]);
                        acc[g][2] = fma2(w2[g][2*j+1], u2.y, acc[g][2]);
                        acc[g][3] = fma2(w2[g][2*j],   u3.x, acc[g][3]);
                        acc[g][3] = fma2(w2[g][2*j+1], u3.y, acc[g][3]);
                    }
                }
                float fin[4][2];
                #pragma unroll
                for (int g = 0; g < 4; ++g)
                    #pragma unroll
                    for (int lb = 0; lb < 2; ++lb) {
                        const float mine  = sum2(ks ? acc[g][2+lb] : acc[g][lb]);
                        const float other = sum2(ks ? acc[g][lb]   : acc[g][2+lb]);
                        fin[g][lb] = mine + __shfl_xor_sync(pmask, other, 1);
                    }
                const float* zr = zring + sl*ZS + zb*ZST;
                const float4 zlo = reinterpret_cast<const float4*>(zr)[0];
                const float4 zhi = reinterpret_cast<const float4*>(zr)[1];
                const float zp[4][2] = {{zlo.x, zlo.y}, {zlo.z, zlo.w},
                                        {zhi.x, zhi.y}, {zhi.z, zhi.w}};
                #pragma unroll
                for (int lb = 0; lb < 2; ++lb) {
                    const int b = 2*ks + lb;
                    const float zi = fin[0][lb] + zp[0][lb] + bz[0];
                    const float zf = fin[1][lb] + zp[1][lb] + bz[1];
                    const float zg = fin[2][lb] + zp[2][lb] + bz[2];
                    const float zo = fin[3][lb] + zp[3][lb] + bz[3];
                    const float ig = sigap(zi), fg = sigap(zf);
                    const float gg = tanhap(zg), og = sigap(zo);
                    c2[lb] = fmaf(fg, c2[lb], ig*gg);
                    h2w[b*HP + unit] = og * tanhap(c2[lb]);
                }
            }
            if (isOut && t >= 1 && t <= TT) {
                const float* h2p = h2b + ((t + 1) & 1)*BHP;   // h2(t-1)
                float v = 0.f;
                #pragma unroll
                for (int m = 0; m < 26; ++m)
                    v = fmaf(h2p[ob*HP + half*26 + m], wo[m], v);
                v += __shfl_xor_sync(pmask, v, 1);
                if (half == 0) out[(row0 + ob)*TT + (t - 1)] = v + blin;
            }
            bar_arrive_n(BEZ + sl);                // z(t) consumed
        }
    }
}

extern "C" void kernel_launch(void* const* d_in, const int* in_sizes, int n_in,
                              void* d_out, int out_size)
{
    const float* input = (const float*)d_in[0];
    const float* W_ih1 = (const float*)d_in[1];
    const float* W_hh1 = (const float*)d_in[2];
    const float* b_ih1 = (const float*)d_in[3];
    const float* b_hh1 = (const float*)d_in[4];
    const float* W_ih2 = (const float*)d_in[5];
    const float* W_hh2 = (const float*)d_in[6];
    const float* b_ih2 = (const float*)d_in[7];
    const float* b_hh2 = (const float*)d_in[8];
    const float* W_lin = (const float*)d_in[9];
    const float* b_lin = (const float*)d_in[10];
    float* out = (float*)d_out;

    lstm2_kernel<<<NBLK, NTH>>>(input, W_ih1, W_hh1, b_ih1, b_hh1,
                                W_ih2, W_hh2, b_ih2, b_hh2,
                                W_lin, b_lin, out);
}

// round 15
// speedup vs baseline: 1.4049x; 1.2504x over previous
#include <cuda_runtime.h>
#include <cstdint>

// 2-layer LSTM (H=51), B=512, T=512, scalar in, linear head, future=0.
// TENSOR-CORE version: per step two tf32 GEMMs via mma.sync.m16n8k8
//   GEMM1: z1[204x4] = Whh1[204x51] x h1[51x4]
//   GEMM2: z2[204x4] = [Wih2|Whh2][204x102] x [h1(t); h2(t-1)][102x4]
// A-fragments pre-swizzled in smem (1 LDS.128 each); h in [k][8] fp32 (B cvt at load).
// 128 blocks, 832 threads (26 warps): S1 = warps 0-12 (GEMM1+combine1),
// S2 = warps 13-25 (GEMM2+combine2+out). Depth-4 F/E named-barrier pipeline.

#define TT    512
#define NTH   832
#define NBLK  128
#define NIT   514
#define MT    13
#define KF1   7
#define KF2   13

#define OFF_A1 0
#define OFF_A2 11648             // + 13*7*32*4
#define OFF_HC 33280             // + 13*13*32*4
#define OFF_Z1 36608             // + 4*832 (hc: 4 slots x 104x8)
#define OFF_Z2 37440             // + 832
#define OFF_X  38272             // + 832
#define OFF_WL 40320             // + 4*512
#define SMEM_FLOATS 40384
#define SMEM_BYTES (SMEM_FLOATS*4)
#define HCS 832                  // floats per hc slot (104*8)

// named barriers: F slots 1-4, E slots 5-8, S1INT 9, S2INT 10
__device__ __forceinline__ void bar_sync_c(int id, int cnt) {
    asm volatile("bar.sync %0, %1;" :: "r"(id), "r"(cnt) : "memory");
}
__device__ __forceinline__ void bar_arrive_c(int id, int cnt) {
    asm volatile("bar.arrive %0, %1;" :: "r"(id), "r"(cnt) : "memory");
}
__device__ __forceinline__ unsigned tf32c(float x) {
    unsigned u; asm("cvt.rna.tf32.f32 %0, %1;" : "=r"(u) : "f"(x)); return u;
}
__device__ __forceinline__ void mma8(float& c0, float& c1, float& c2, float& c3,
                                     uint4 a, unsigned b0, unsigned b1) {
    asm volatile("mma.sync.aligned.m16n8k8.row.col.f32.tf32.tf32.f32 "
        "{%0,%1,%2,%3}, {%4,%5,%6,%7}, {%8,%9}, {%0,%1,%2,%3};"
        : "+f"(c0), "+f"(c1), "+f"(c2), "+f"(c3)
        : "r"(a.x), "r"(a.y), "r"(a.z), "r"(a.w), "r"(b0), "r"(b1));
}
__device__ __forceinline__ float tanhap(float x) {
    float y; asm("tanh.approx.f32 %0, %1;" : "=f"(y) : "f"(x)); return y;
}
__device__ __forceinline__ float sigap(float x) {
    return fmaf(0.5f, tanhap(0.5f * x), 0.5f);
}

extern __shared__ float smem[];

__global__ __launch_bounds__(NTH, 1)
void lstm2_kernel(const float* __restrict__ input,
                  const float* __restrict__ W_ih1,
                  const float* __restrict__ W_hh1,
                  const float* __restrict__ b_ih1,
                  const float* __restrict__ b_hh1,
                  const float* __restrict__ W_ih2,
                  const float* __restrict__ W_hh2,
                  const float* __restrict__ b_ih2,
                  const float* __restrict__ b_hh2,
                  const float* __restrict__ W_lin,
                  const float* __restrict__ b_lin,
                  float* __restrict__ out)
{
    float* const a1f  = smem + OFF_A1;
    float* const a2f  = smem + OFF_A2;
    float* const hc   = smem + OFF_HC;   // [4][104][8]; rows0-50 h1, 51-101 h2
    float* const z1   = smem + OFF_Z1;   // [208][4]
    float* const z2   = smem + OFF_Z2;
    float* const xall = smem + OFF_X;    // [4][512]
    float* const wl   = smem + OFF_WL;   // [56]

    const int tid  = threadIdx.x;
    const int lane = tid & 31;
    const int g    = lane >> 2;          // mma group 0-7
    const int tq   = lane & 3;           // mma thread-in-group
    const int row0 = blockIdx.x * 4;

    const bool isS1 = (tid < 416);
    const int  sw   = (isS1 ? tid : tid - 416) >> 5;   // stage warp 0-12
    const int  idx  = isS1 ? tid : tid - 416;          // 0-415
    const bool isC  = (idx < 204);
    const int  cu   = idx >> 2;          // unit 0-50
    const int  cb   = idx & 3;           // batch 0-3
    const bool isOut = (!isS1) && (idx >= 204 && idx < 212);

    // ---- stage A1 fragments (Whh1, tf32, zero-padded) ----
    for (int e = tid; e < MT*KF1*32; e += NTH) {
        const int w  = e / (KF1*32);
        const int rm = e - w*(KF1*32);
        const int kf = rm >> 5;
        const int ln = rm & 31;
        const int gg = ln >> 2, tt = ln & 3;
        const int r0 = 16*w + gg, k0 = 8*kf + tt;
        float4 v;
        v.x = (r0   < 204 && k0   < 51) ? __uint_as_float(tf32c(W_hh1[ r0   *51 + k0  ])) : 0.0f;
        v.y = (r0+8 < 204 && k0   < 51) ? __uint_as_float(tf32c(W_hh1[(r0+8)*51 + k0  ])) : 0.0f;
        v.z = (r0   < 204 && k0+4 < 51) ? __uint_as_float(tf32c(W_hh1[ r0   *51 + k0+4])) : 0.0f;
        v.w = (r0+8 < 204 && k0+4 < 51) ? __uint_as_float(tf32c(W_hh1[(r0+8)*51 + k0+4])) : 0.0f;
        reinterpret_cast<float4*>(a1f)[e] = v;
    }
    // ---- stage A2 fragments ([Wih2 | Whh2], K=102) ----
    for (int e = tid; e < MT*KF2*32; e += NTH) {
        const int w  = e / (KF2*32);
        const int rm = e - w*(KF2*32);
        const int kf = rm >> 5;
        const int ln = rm & 31;
        const int gg = ln >> 2, tt = ln & 3;
        const int r0 = 16*w + gg, k0 = 8*kf + tt;
        float4 v; float* pv = &v.x;
        #pragma unroll
        for (int q2 = 0; q2 < 4; ++q2) {
            const int r = r0 + (q2 & 1)*8;
            const int k = k0 + (q2 >> 1)*4;
            float val = 0.0f;
            if (r < 204 && k < 102)
                val = (k < 51) ? W_ih2[r*51 + k] : W_hh2[r*51 + (k - 51)];
            pv[q2] = __uint_as_float(tf32c(val));
        }
        reinterpret_cast<float4*>(a2f)[e] = v;
    }
    // zero hc, z, wl; load x
    for (int i = tid; i < 4*HCS; i += NTH) hc[i] = 0.0f;
    for (int i = tid; i < 2*832;  i += NTH) z1[i] = 0.0f;    // z1+z2 contiguous
    for (int i = tid; i < 56;     i += NTH) wl[i] = (i < 51) ? W_lin[i] : 0.0f;
    for (int i = tid; i < 4*TT;   i += NTH) {
        const int b = i >> 9;
        const int t = i & (TT - 1);
        xall[i] = input[(row0 + b)*TT + t];
    }

    // ---- combine constants ----
    float wx[4] = {0,0,0,0}, bz[4] = {0,0,0,0};
    if (isC) {
        #pragma unroll
        for (int g4 = 0; g4 < 4; ++g4) {
            const int r = cu + 51*g4;
            if (isS1) { wx[g4] = W_ih1[r]; bz[g4] = b_ih1[r] + b_hh1[r]; }
            else      {                    bz[g4] = b_ih2[r] + b_hh2[r]; }
        }
    }
    float blin = 0.0f; int ob = 0, half = 0;
    if (isOut) { const int o = idx - 204; ob = o >> 1; half = o & 1; blin = b_lin[0]; }
    const unsigned pmask = 0x3u << (lane & 30);

    float cst = 0.0f;
    __syncthreads();

    if (isS1) {
        // ================= S1: GEMM1 + combine1 -> h1 =================
        const float* afb = a1f + sw*(KF1*32*4);
        for (int i = 0; i < NIT; ++i) {
            bar_sync_c(5 + (i & 3), NTH);                 // slot free + S1 rendezvous
            if (i < TT) {
                const float* hin = hc + ((i + 3) & 3)*HCS;   // h1(i-1) rows 0-50
                float c0 = 0.f, c1 = 0.f, c2 = 0.f, c3 = 0.f;
                #pragma unroll
                for (int kf = 0; kf < KF1; ++kf) {
                    const uint4 a = reinterpret_cast<const uint4*>(afb)[kf*32 + lane];
                    const unsigned b0 = tf32c(hin[(8*kf + tq    )*8 + g]);
                    const unsigned b1 = tf32c(hin[(8*kf + tq + 4)*8 + g]);
                    mma8(c0, c1, c2, c3, a, b0, b1);
                }
                if (tq < 2) {
                    const int r0 = 16*sw + g;
                    *reinterpret_cast<float2*>(z1 +  r0     *4 + 2*tq) = make_float2(c0, c1);
                    *reinterpret_cast<float2*>(z1 + (r0 + 8)*4 + 2*tq) = make_float2(c2, c3);
                }
            }
            bar_sync_c(9, 416);                           // z1 ready
            if (i < TT && isC) {
                const float xv = xall[cb*TT + i];
                const float zi = z1[ cu       *4 + cb] + fmaf(xv, wx[0], bz[0]);
                const float zf = z1[(cu +  51)*4 + cb] + fmaf(xv, wx[1], bz[1]);
                const float zg = z1[(cu + 102)*4 + cb] + fmaf(xv, wx[2], bz[2]);
                const float zo = z1[(cu + 153)*4 + cb] + fmaf(xv, wx[3], bz[3]);
                const float ig = sigap(zi), fg = sigap(zf);
                const float gg = tanhap(zg), og = sigap(zo);
                cst = fmaf(fg, cst, ig*gg);
                hc[(i & 3)*HCS + cu*8 + cb] = og * tanhap(cst);
            }
            bar_arrive_c(1 + (i & 3), NTH);               // h1(i) published
        }
    } else {
        // ================= S2: GEMM2 + combine2 -> h2; out head =================
        bar_arrive_c(5, NTH); bar_arrive_c(6, NTH);
        bar_arrive_c(7, NTH); bar_arrive_c(8, NTH);       // pre-seed E slots
        const float* afb = a2f + sw*(KF2*32*4);
        for (int i = 0; i < NIT; ++i) {
            if (i >= 1) bar_sync_c(1 + ((i - 1) & 3), NTH);   // h1(i-1) ready
            if (isOut && i >= 2) {
                // out(i-2) from h2(i-2) in slot (i-1)&3 rows 51..101 (written iter i-1)
                const float* h2p = hc + ((i - 1) & 3)*HCS;
                float v = 0.f;
                #pragma unroll
                for (int m = 0; m < 26; ++m) {
                    const int j = half*26 + m;
                    v = fmaf(h2p[(51 + j)*8 + ob], wl[j], v);
                }
                v += __shfl_xor_sync(pmask, v, 1);
                if (half == 0) out[(row0 + ob)*TT + (i - 2)] = v + blin;
            }
            if (i >= 1 && i <= TT) {
                const float* hin = hc + ((i - 1) & 3)*HCS;   // rows 0-103: h1(i-1), h2(i-2)
                float c0 = 0.f, c1 = 0.f, c2 = 0.f, c3 = 0.f;
                #pragma unroll
                for (int kf = 0; kf < KF2; ++kf) {
                    const uint4 a = reinterpret_cast<const uint4*>(afb)[kf*32 + lane];
                    const unsigned b0 = tf32c(hin[(8*kf + tq    )*8 + g]);
                    const unsigned b1 = tf32c(hin[(8*kf + tq + 4)*8 + g]);
                    mma8(c0, c1, c2, c3, a, b0, b1);
                }
                if (tq < 2) {
                    const int r0 = 16*sw + g;
                    *reinterpret_cast<float2*>(z2 +  r0     *4 + 2*tq) = make_float2(c0, c1);
                    *reinterpret_cast<float2*>(z2 + (r0 + 8)*4 + 2*tq) = make_float2(c2, c3);
                }
            }
            bar_sync_c(10, 416);                          // z2 ready
            if (i >= 1 && i <= TT && isC) {
                const float zi = z2[ cu       *4 + cb] + bz[0];
                const float zf = z2[(cu +  51)*4 + cb] + bz[1];
                const float zg = z2[(cu + 102)*4 + cb] + bz[2];
                const float zo = z2[(cu + 153)*4 + cb] + bz[3];
                const float ig = sigap(zi), fg = sigap(zf);
                const float gg = tanhap(zg), og = sigap(zo);
                cst = fmaf(fg, cst, ig*gg);
                // h2(i-1) -> slot i&3 rows 51+ (read by GEMM2 at iter i+1)
                hc[(i & 3)*HCS + (51 + cu)*8 + cb] = og * tanhap(cst);
            }
            if (i >= 1) bar_arrive_c(5 + ((i - 1) & 3), NTH);  // slot consumed
        }
    }
}

extern "C" void kernel_launch(void* const* d_in, const int* in_sizes, int n_in,
                              void* d_out, int out_size)
{
    const float* input = (const float*)d_in[0];
    const float* W_ih1 = (const float*)d_in[1];
    const float* W_hh1 = (const float*)d_in[2];
    const float* b_ih1 = (const float*)d_in[3];
    const float* b_hh1 = (const float*)d_in[4];
    const float* W_ih2 = (const float*)d_in[5];
    const float* W_hh2 = (const float*)d_in[6];
    const float* b_ih2 = (const float*)d_in[7];
    const float* b_hh2 = (const float*)d_in[8];
    const float* W_lin = (const float*)d_in[9];
    const float* b_lin = (const float*)d_in[10];
    float* out = (float*)d_out;

    cudaFuncSetAttribute(lstm2_kernel,
                         cudaFuncAttributeMaxDynamicSharedMemorySize, SMEM_BYTES);
    lstm2_kernel<<<NBLK, NTH, SMEM_BYTES>>>(input, W_ih1, W_hh1, b_ih1, b_hh1,
                                            W_ih2, W_hh2, b_ih2, b_hh2,
                                            W_lin, b_lin, out);
}